// round 17
// baseline (speedup 1.0000x reference)
#include <cuda_runtime.h>
#include <cuda_bf16.h>
#include <cstdint>

// Problem constants (fixed shapes)
constexpr int DIN      = 1024;   // input dim
constexpr int L        = 65;     // NUM_FREQ + 1
constexpr int N1       = 130;    // 2L (GEMM1 output cols)
constexpr int F        = 64;     // NUM_FREQ
constexpr int K2       = 128;    // 2F (GEMM2 reduction)
constexpr int D        = 512;    // DIM_OUTPUT
constexpr int ROWS_MAX = 65536;  // 16 * 4096

// GEMM1 mma tiling: M=64/CTA; 8 warps = 2 row-halves (32 rows) x 4 nt-groups
constexpr int NTILES  = 17;            // 136 cols / 8
constexpr int KSTEPS  = 64;            // 1024 / 16, one kstep per pipeline stage
constexpr int KSTEP_U32 = NTILES * 32 * 4;           // 2176 u32 = 8704 B per kstep (B frags)
constexpr int M_CTA   = 64;

// gemm1 pipeline: 3-buffer ring, 1 kstep per stage
constexpr int G1_BST   = 8704;             // B bytes per stage
constexpr int G1_XROWB = 96;               // X smem row stride (2-way conflicts max)
constexpr int G1_XST   = M_CTA * G1_XROWB; // 6144 B per stage
constexpr int G1_STAGE = G1_BST + G1_XST;  // 14848
constexpr int G1_BCH   = G1_BST / 16;      // 544 16B chunks
constexpr int G1_XDATA = M_CTA * 4;        // 256 chunks (4 x 16B per row)
constexpr int G1_CHUNKS = G1_BCH + G1_XDATA;   // 800

// GEMM2 mma tiling: per CTA 128 rows x 128 cols, K=128 (8 ksteps), 16 ntiles
constexpr int G2_NT   = 16;
constexpr int G2_KS   = 8;
constexpr int TFRAG_U32_PER_NT = G2_KS * 32 * 4;         // 1024 u32 per (global) ntile
constexpr int TFRAG_U32 = 64 * TFRAG_U32_PER_NT;         // 65536 u32 = 256 KB total
constexpr int SM2_U32  = G2_NT * TFRAG_U32_PER_NT;       // 16384 u32 = 64 KB per CTA
constexpr int SM2_BYTES = SM2_U32 * 4;

// Scratch (static device globals — no runtime allocation)
// coef in mma A-fragment layout: [rowblock][ks][lane][reg] u32 (2 bf16 per u32)
constexpr size_t COEF_U32 = (size_t)(ROWS_MAX / 16) * 8 * 32 * 4;
__device__ __align__(16) uint32_t g_coef_fh[COEF_U32];
__device__ __align__(16) uint32_t g_coef_fl[COEF_U32];
__device__ float g_CS[F];
__device__ float g_SS[F];
__device__ float g_invS[ROWS_MAX];
// GEMM1 B fragments: [ks][ntile][lane][4] = {bh0,bh1,bl0,bl1}
__device__ __align__(16) uint32_t g_Bfrag[(size_t)KSTEPS * KSTEP_U32];
// GEMM2 B fragments (T table): [nt][ks][lane][4] = {bh0,bh1,bl0,bl1}
__device__ __align__(16) uint32_t g_Tfrag[(size_t)TFRAG_U32];

// ---- helpers ----
__device__ __forceinline__ uint32_t smem_u32(const void* p) {
    uint32_t a;
    asm("{ .reg .u64 t; cvta.to.shared.u64 t, %1; cvt.u32.u64 %0, t; }" : "=r"(a) : "l"(p));
    return a;
}
__device__ __forceinline__ uint32_t pack_hi(float2 v) {
    __nv_bfloat162 h = __floats2bfloat162_rn(v.x, v.y);
    return *(uint32_t*)&h;
}
__device__ __forceinline__ uint32_t pack_lo(float2 v, uint32_t hp) {
    __nv_bfloat162 h = *(__nv_bfloat162*)&hp;
    float rx = v.x - __bfloat162float(h.x);
    float ry = v.y - __bfloat162float(h.y);
    __nv_bfloat162 lo = __floats2bfloat162_rn(rx, ry);
    return *(uint32_t*)&lo;
}
__device__ __forceinline__ void mma_bf16(float* c, uint32_t a0, uint32_t a1,
                                         uint32_t a2, uint32_t a3,
                                         uint32_t b0, uint32_t b1) {
    asm volatile(
        "mma.sync.aligned.m16n8k16.row.col.f32.bf16.bf16.f32 "
        "{%0,%1,%2,%3}, {%4,%5,%6,%7}, {%8,%9}, {%0,%1,%2,%3};"
        : "+f"(c[0]), "+f"(c[1]), "+f"(c[2]), "+f"(c[3])
        : "r"(a0), "r"(a1), "r"(a2), "r"(a3), "r"(b0), "r"(b1));
}
#define CPA16(dst_u32, src_ptr) \
    asm volatile("cp.async.cg.shared.global [%0], [%1], 16;" :: "r"(dst_u32), "l"(src_ptr) : "memory")
#define CPA_COMMIT() asm volatile("cp.async.commit_group;" ::: "memory")
#define CPA_WAIT1()  asm volatile("cp.async.wait_group 1;" ::: "memory")
#define CPA_WAIT0()  asm volatile("cp.async.wait_group 0;" ::: "memory")

// ============================================================
// Kernel 0: column sums of cos/sin table (CS/SS only)
// ============================================================
__global__ void table_kernel() {
    const int f = blockIdx.x;
    const int d = threadIdx.x;
    float center = -1.0f + (2 * d + 1) * (1.0f / 512.0f);
    float arg = center * (float)(f + 1);
    float s, c;
    sincospif(arg, &s, &c);

    __shared__ float sc[512], ss[512];
    sc[d] = c;
    ss[d] = s;
    __syncthreads();
    for (int off = 256; off > 0; off >>= 1) {
        if (d < off) {
            sc[d] += sc[d + off];
            ss[d] += ss[d + off];
        }
        __syncthreads();
    }
    if (d == 0) {
        g_CS[f] = sc[0];
        g_SS[f] = ss[0];
    }
}

// ============================================================
// Kernel 0b: W -> bf16 hi/lo mma B-fragments (GEMM1)
// layout: [ks][nt][lane][4] = {bh0, bh1, bl0, bl1}
// ============================================================
__global__ void wprep_kernel(const float* __restrict__ Wm) {
    const int ks = blockIdx.x;
    const int nt = threadIdx.x >> 5;
    const int lane = threadIdx.x & 31;
    const int n = nt * 8 + (lane >> 2);
    const int kc = ks * 16 + (lane & 3) * 2;
    float2 wa = make_float2(0.f, 0.f), wb = make_float2(0.f, 0.f);
    if (n < N1) {
        const float* wr = Wm + (size_t)n * DIN;
        wa = make_float2(wr[kc], wr[kc + 1]);
        wb = make_float2(wr[kc + 8], wr[kc + 9]);
    }
    uint32_t h0 = pack_hi(wa), h1 = pack_hi(wb);
    uint32_t l0 = pack_lo(wa, h0), l1 = pack_lo(wb, h1);
    size_t idx = (((size_t)ks * NTILES + nt) * 32 + lane) * 4;
    g_Bfrag[idx + 0] = h0;
    g_Bfrag[idx + 1] = h1;
    g_Bfrag[idx + 2] = l0;
    g_Bfrag[idx + 3] = l1;
}

// ============================================================
// Kernel 0c: T table -> bf16 hi/lo mma B-fragments (GEMM2)
// layout: [nt][ks][lane][4] = {bh0, bh1, bl0, bl1}
// ============================================================
__device__ __forceinline__ float tval(int k, float center) {
    float s, c;
    if (k < F) {
        sincospif(center * (float)(k + 1), &s, &c);
        return c;
    } else {
        sincospif(center * (float)(k - F + 1), &s, &c);
        return -s;
    }
}
__global__ void tprep_kernel() {
    const int nt = blockIdx.x;
    const int ks = threadIdx.x >> 5;
    const int lane = threadIdx.x & 31;
    const int n = nt * 8 + (lane >> 2);
    const int kc = ks * 16 + (lane & 3) * 2;
    float center = -1.0f + (2 * n + 1) * (1.0f / 512.0f);
    float2 va = make_float2(tval(kc, center), tval(kc + 1, center));
    float2 vb = make_float2(tval(kc + 8, center), tval(kc + 9, center));
    uint32_t h0 = pack_hi(va), h1 = pack_hi(vb);
    uint32_t l0 = pack_lo(va, h0), l1 = pack_lo(vb, h1);
    size_t idx = (((size_t)nt * G2_KS + ks) * 32 + lane) * 4;
    g_Tfrag[idx + 0] = h0;
    g_Tfrag[idx + 1] = h1;
    g_Tfrag[idx + 2] = l0;
    g_Tfrag[idx + 3] = l1;
}

// ============================================================
// coef fragment-layout writer: element (grow, col), value v ->
// hi/lo bf16 at [rowblock][ks][lane][reg][half]
// ============================================================
__device__ __forceinline__ void write_coef(int grow, int col, float v) {
    int rb = grow >> 4, r = grow & 15;
    int ks = col >> 4, kc = col & 15;
    int lane2 = (r & 7) * 4 + ((kc & 7) >> 1);
    int reg = (r >> 3) | ((kc >> 3) << 1);
    int half = kc & 1;
    size_t uoff = (((size_t)rb * 8 + ks) * 32 + lane2) * 4 + reg;
    __nv_bfloat16 vh = __float2bfloat16(v);
    ((__nv_bfloat16*)g_coef_fh)[uoff * 2 + half] = vh;
    ((__nv_bfloat16*)g_coef_fl)[uoff * 2 + half] =
        __float2bfloat16(v - __bfloat162float(vh));
}

// ============================================================
// Kernel 1 (HMMA, cp.async 3-stage ring, 4 CTAs/SM):
// M=64 rows/CTA. Warp = 2 row-slices (rows rh*32.. and +16) x nt-group
// ({5,4,4,4} over 17, compile-time specialized). Each B fragment LDS.128
// is consumed by 6 MMAs (2 slices x 3 products) -> half the B smem traffic.
// Epilogue: sliding-window 4-lag autocorr (zero-padded rows).
// ============================================================
constexpr int ZSTR  = 69;                            // complex stride per row (zero-padded)
constexpr int SM_PZ    = 0;                          // 64 x 69 float2 = 35328
constexpr int SM_CONTR = 35328;                      // 64*64 f32 -> 51712
constexpr int SM_INVR  = 51712;                      // 64 f32 -> 51968
constexpr int SM_BIAS  = 51968;                      // 136 f32 -> 52512
constexpr int SM1_BYTES = 52512 + 64;
// ring occupies [0, 44544); overlay used only after mainloop

template <int NT0, int NTN>
__device__ __forceinline__ void mma_group(
    float (&a0)[5][4], float (&a1)[5][4], const char* kbase,
    uint32_t h00, uint32_t h01, uint32_t h02, uint32_t h03,
    uint32_t l00, uint32_t l01, uint32_t l02, uint32_t l03,
    uint32_t h10, uint32_t h11, uint32_t h12, uint32_t h13,
    uint32_t l10, uint32_t l11, uint32_t l12, uint32_t l13) {
#pragma unroll
    for (int nt = 0; nt < NTN; nt++) {
        uint4 f = *(const uint4*)(kbase + (NT0 + nt) * 512);
        mma_bf16(a0[nt], h00, h01, h02, h03, f.x, f.y);
        mma_bf16(a0[nt], h00, h01, h02, h03, f.z, f.w);
        mma_bf16(a0[nt], l00, l01, l02, l03, f.x, f.y);
        mma_bf16(a1[nt], h10, h11, h12, h13, f.x, f.y);
        mma_bf16(a1[nt], h10, h11, h12, h13, f.z, f.w);
        mma_bf16(a1[nt], l10, l11, l12, l13, f.x, f.y);
    }
}

__global__ void __launch_bounds__(256, 4)
gemm1_mma_kernel(const float* __restrict__ X, const float* __restrict__ bias) {
    extern __shared__ char sm[];
    const uint32_t sb = smem_u32(sm);
    const int tid = threadIdx.x;
    const int w = tid >> 5;
    const int lane = tid & 31;
    const int ng = w & 3;            // ntile group: {0-4, 5-8, 9-12, 13-16}
    const int rh = w >> 2;           // row half (32 rows)
    const int m0 = blockIdx.x * M_CTA;

    if (tid < 136) ((float*)(sm + SM_BIAS))[tid] = (tid < N1) ? bias[tid] : 0.0f;

    float acc0[5][4], acc1[5][4];
#pragma unroll
    for (int nt = 0; nt < 5; nt++)
#pragma unroll
        for (int i = 0; i < 4; i++) { acc0[nt][i] = 0.0f; acc1[nt][i] = 0.0f; }

    const char* gB = (const char*)g_Bfrag;

    // stage copy: B chunk ids [0,544), X chunk ids [544,800)
    auto copy_stage = [&](int s, int buf) {
        const uint32_t dstb = sb + buf * G1_STAGE;
        const char* srcB = gB + (size_t)s * G1_BST;
#pragma unroll
        for (int it = 0; it < 4; it++) {
            int i = tid + 256 * it;
            if (i < G1_BCH) {
                CPA16(dstb + i * 16, srcB + i * 16);
            } else if (i < G1_CHUNKS) {
                int j = i - G1_BCH;
                int row = j >> 2;
                int c4 = j & 3;
                const float* src = X + (size_t)(m0 + row) * DIN + s * 16 + c4 * 4;
                CPA16(dstb + G1_BST + row * G1_XROWB + c4 * 16, src);
            }
        }
    };

    copy_stage(0, 0); CPA_COMMIT();
    copy_stage(1, 1); CPA_COMMIT();

    const int xoff0 = (rh * 32 + (lane >> 2)) * G1_XROWB + (lane & 3) * 8;
    const int xoff1 = xoff0 + 16 * G1_XROWB;

    int cur = 0;                     // buffer of stage s
    for (int s = 0; s < KSTEPS; s++) {
        if (s < KSTEPS - 1) { CPA_WAIT1(); }
        else                { CPA_WAIT0(); }
        __syncthreads();
        if (s + 2 < KSTEPS) {
            int tgt = cur ? cur - 1 : 2;     // (cur + 2) % 3
            copy_stage(s + 2, tgt);
            CPA_COMMIT();
        }

        const char* bb = sm + cur * G1_STAGE;

        // A fragments, slice 0
        const char* xb0 = bb + G1_BST + xoff0;
        float2 s0v1a = *(const float2*)(xb0);
        float2 s0v1b = *(const float2*)(xb0 + 32);
        float2 s0v2a = *(const float2*)(xb0 + 8 * G1_XROWB);
        float2 s0v2b = *(const float2*)(xb0 + 8 * G1_XROWB + 32);
        uint32_t h00 = pack_hi(s0v1a), h01 = pack_hi(s0v2a);
        uint32_t h02 = pack_hi(s0v1b), h03 = pack_hi(s0v2b);
        uint32_t l00 = pack_lo(s0v1a, h00), l01 = pack_lo(s0v2a, h01);
        uint32_t l02 = pack_lo(s0v1b, h02), l03 = pack_lo(s0v2b, h03);
        // A fragments, slice 1
        const char* xb1 = bb + G1_BST + xoff1;
        float2 s1v1a = *(const float2*)(xb1);
        float2 s1v1b = *(const float2*)(xb1 + 32);
        float2 s1v2a = *(const float2*)(xb1 + 8 * G1_XROWB);
        float2 s1v2b = *(const float2*)(xb1 + 8 * G1_XROWB + 32);
        uint32_t h10 = pack_hi(s1v1a), h11 = pack_hi(s1v2a);
        uint32_t h12 = pack_hi(s1v1b), h13 = pack_hi(s1v2b);
        uint32_t l10 = pack_lo(s1v1a, h10), l11 = pack_lo(s1v2a, h11);
        uint32_t l12 = pack_lo(s1v1b, h12), l13 = pack_lo(s1v2b, h13);

        const char* kbase = bb + lane * 16;
        if (ng == 0) {
            mma_group<0, 5>(acc0, acc1, kbase, h00, h01, h02, h03, l00, l01, l02, l03,
                            h10, h11, h12, h13, l10, l11, l12, l13);
        } else if (ng == 1) {
            mma_group<5, 4>(acc0, acc1, kbase, h00, h01, h02, h03, l00, l01, l02, l03,
                            h10, h11, h12, h13, l10, l11, l12, l13);
        } else if (ng == 2) {
            mma_group<9, 4>(acc0, acc1, kbase, h00, h01, h02, h03, l00, l01, l02, l03,
                            h10, h11, h12, h13, l10, l11, l12, l13);
        } else {
            mma_group<13, 4>(acc0, acc1, kbase, h00, h01, h02, h03, l00, l01, l02, l03,
                             h10, h11, h12, h13, l10, l11, l12, l13);
        }
        cur = (cur == 2) ? 0 : cur + 1;
    }
    __syncthreads();   // ring dead; overlay pz

    // ---- scatter acc (+bias) into interleaved pz[row][c], zero pad ----
    // c < 65: z.x = p[c];  c >= 65: z[c-65].y = p[c]
    float* pzf = (float*)(sm + SM_PZ);
    float* sbias = (float*)(sm + SM_BIAS);
    // zero the pad region: complex [65..68] per row = floats [130..137]
    for (int i = tid; i < M_CTA * 8; i += 256) {
        int row = i >> 3;
        pzf[row * (2 * ZSTR) + 130 + (i & 7)] = 0.0f;
    }
    {
        const int cb = (lane & 3) * 2;
        const int NTN = (ng == 0) ? 5 : 4;
        const int NT0 = (ng == 0) ? 0 : 1 + ng * 4;
#pragma unroll
        for (int sl = 0; sl < 2; sl++) {
            const int rbase = rh * 32 + sl * 16 + (lane >> 2);
            for (int nt = 0; nt < NTN; nt++) {
                int col0 = (NT0 + nt) * 8 + cb;
#pragma unroll
                for (int h = 0; h < 2; h++) {
                    int col = col0 + h;
                    if (col < N1) {
                        float bv = sbias[col];
                        float v0 = (sl ? acc1 : acc0)[nt][h] + bv;       // row rbase
                        float v1 = (sl ? acc1 : acc0)[nt][2 + h] + bv;   // row rbase+8
                        int ci = (col < L) ? col * 2 : (col - L) * 2 + 1;
                        pzf[rbase * (2 * ZSTR) + ci] = v0;
                        pzf[(rbase + 8) * (2 * ZSTR) + ci] = v1;
                    }
                }
            }
        }
    }
    __syncthreads();

    // ---- autocorrelation: sliding-window, 4 lags per thread ----
    const float2* pz = (const float2*)(sm + SM_PZ);
    float* contrib = (float*)(sm + SM_CONTR);
    float* inv_r0 = (float*)(sm + SM_INVR);

    if (tid < M_CTA) {
        const float2* zr = pz + tid * ZSTR;
        float s = 0.0f;
        for (int j = 0; j < L; j++) {
            float2 u = zr[j];
            s += u.x * u.x + u.y * u.y;
        }
        inv_r0[tid] = 1.0f / s;
    }
    __syncthreads();

    // tasks: (row, lag-group). lane -> row (contiguous rows per warp,
    // identical lag-group per warp => balanced, ~2-way conflicts at stride 69)
#pragma unroll
    for (int it = 0; it < 4; it++) {
        const int row = tid & 63;
        const int lag4 = (tid >> 6) + 4 * it;    // 0..15
        const int lag0 = 1 + 4 * lag4;
        const float2* zr = pz + row * ZSTR;

        float2 w0 = zr[lag0], w1 = zr[lag0 + 1], w2 = zr[lag0 + 2], w3 = zr[lag0 + 3];
        float sr0 = 0.f, si0 = 0.f, sr1 = 0.f, si1 = 0.f;
        float sr2 = 0.f, si2 = 0.f, sr3 = 0.f, si3 = 0.f;
        const int n = L - lag0;
        for (int j = 0; j < n; j++) {
            float2 v = zr[j];
            sr0 += w0.x * v.x + w0.y * v.y;  si0 += w0.y * v.x - w0.x * v.y;
            sr1 += w1.x * v.x + w1.y * v.y;  si1 += w1.y * v.x - w1.x * v.y;
            sr2 += w2.x * v.x + w2.y * v.y;  si2 += w2.y * v.x - w2.x * v.y;
            sr3 += w3.x * v.x + w3.y * v.y;  si3 += w3.y * v.x - w3.x * v.y;
            w0 = w1; w1 = w2; w2 = w3;
            w3 = zr[j + lag0 + 4];
        }
        float ir = inv_r0[row];
        float srs[4] = {sr0, sr1, sr2, sr3};
        float sis[4] = {si0, si1, si2, si3};
#pragma unroll
        for (int i = 0; i < 4; i++) {
            int lag = lag0 + i;
            float cr = srs[i] * ir;
            float ci_ = sis[i] * ir;
            write_coef(m0 + row, lag - 1, cr);
            write_coef(m0 + row, F + lag - 1, ci_);
            contrib[row * 64 + (lag - 1)] = cr * g_CS[lag - 1] - ci_ * g_SS[lag - 1];
        }
    }
    __syncthreads();

    if (tid < M_CTA) {
        const float* cb = contrib + tid * 64;
        float S = 0.5f * (float)D;
        for (int k = 0; k < 64; k++) S += cb[k];
        g_invS[m0 + tid] = 1.0f / S;
    }
}

// ============================================================
// Kernel 2 (HMMA): like = coef @ T (+0.5) -> log epilogue
// A: 2 LDG.128 per warp per ks (coef fragment layout);
// B: 1 LDS.128 per (ntile, ks).
// ============================================================
__global__ void __launch_bounds__(256)
gemm2_mma_kernel(float* __restrict__ out) {
    extern __shared__ char sm[];
    uint32_t* smB = (uint32_t*)sm;
    const int tid = threadIdx.x;
    const int w = tid >> 5;
    const int lane = tid & 31;
    const int m0 = blockIdx.x * 128;
    const int nb = blockIdx.y;

    {
        const uint4* src = (const uint4*)(g_Tfrag + (size_t)nb * SM2_U32);
        uint4* dst = (uint4*)smB;
        for (int i = tid; i < SM2_U32 / 4; i += 256) dst[i] = src[i];
    }
    __syncthreads();

    float acc[G2_NT][4];
#pragma unroll
    for (int nt = 0; nt < G2_NT; nt++)
#pragma unroll
        for (int i = 0; i < 4; i++) acc[nt][i] = 0.0f;

    const int rb = blockIdx.x * 8 + w;     // global 16-row block
    const uint4* cfh = (const uint4*)g_coef_fh + ((size_t)rb * 8) * 32 + lane;
    const uint4* cfl = (const uint4*)g_coef_fl + ((size_t)rb * 8) * 32 + lane;
    const uint4* smB4 = (const uint4*)smB;

#pragma unroll
    for (int ks = 0; ks < G2_KS; ks++) {
        uint4 Ah = cfh[ks * 32];
        uint4 Al = cfl[ks * 32];
#pragma unroll
        for (int nt = 0; nt < G2_NT; nt++) {
            uint4 f = smB4[(nt * G2_KS + ks) * 32 + lane];
            mma_bf16(acc[nt], Ah.x, Ah.y, Ah.z, Ah.w, f.x, f.y);
            mma_bf16(acc[nt], Ah.x, Ah.y, Ah.z, Ah.w, f.z, f.w);
            mma_bf16(acc[nt], Al.x, Al.y, Al.z, Al.w, f.x, f.y);
        }
    }

    const int r1 = m0 + w * 16 + (lane >> 2);
    const int kc0 = (lane & 3) * 2;
    const float is0 = g_invS[r1];
    const float is1 = g_invS[r1 + 8];
    float* o0 = out + (size_t)r1 * D + nb * 128 + kc0;
    float* o1 = o0 + 8 * (size_t)D;
#pragma unroll
    for (int nt = 0; nt < G2_NT; nt++) {
        float2 u0, u1;
        u0.x = __logf(fmaf(acc[nt][0] + 0.5f, is0, 1e-5f));
        u0.y = __logf(fmaf(acc[nt][1] + 0.5f, is0, 1e-5f));
        u1.x = __logf(fmaf(acc[nt][2] + 0.5f, is1, 1e-5f));
        u1.y = __logf(fmaf(acc[nt][3] + 0.5f, is1, 1e-5f));
        *(float2*)(o0 + nt * 8) = u0;
        *(float2*)(o1 + nt * 8) = u1;
    }
}

extern "C" void kernel_launch(void* const* d_in, const int* in_sizes, int n_in,
                              void* d_out, int out_size) {
    const float* X = (const float*)d_in[0];     // batch [16,4096,1024]
    const float* Wm = (const float*)d_in[1];    // W [130,1024]
    const float* bias = (const float*)d_in[2];  // b [130]
    float* out = (float*)d_out;                 // [16,4096,512] f32

    const int rows = in_sizes[0] / DIN;         // 65536

    static bool attr_set = false;
    if (!attr_set) {
        cudaFuncSetAttribute(gemm1_mma_kernel,
                             cudaFuncAttributeMaxDynamicSharedMemorySize, SM1_BYTES);
        cudaFuncSetAttribute(gemm2_mma_kernel,
                             cudaFuncAttributeMaxDynamicSharedMemorySize, SM2_BYTES);
        attr_set = true;
    }

    table_kernel<<<F, D>>>();
    wprep_kernel<<<KSTEPS, NTILES * 32>>>(Wm);
    tprep_kernel<<<64, 256>>>();
    gemm1_mma_kernel<<<rows / M_CTA, 256, SM1_BYTES>>>(X, bias);
    gemm2_mma_kernel<<<dim3(rows / 128, 4), 256, SM2_BYTES>>>(out);
}